// round 2
// baseline (speedup 1.0000x reference)
#include <cuda_runtime.h>
#include <cuda_fp16.h>
#include <cstdint>

#define NB 4
#define NA 4096
#define ND 128

__device__ __half g_Qh[NB * NA * ND];
__device__ __half g_Kh[NB * NA * ND];
__device__ __half g_Vt[NB * ND * NA];   // [b][d][a]
__device__ float  g_H [NB * NA * ND];

__device__ __forceinline__ void mma_f16(float c[4],
                                        uint32_t a0, uint32_t a1, uint32_t a2, uint32_t a3,
                                        uint32_t b0, uint32_t b1) {
    asm volatile(
        "mma.sync.aligned.m16n8k16.row.col.f32.f16.f16.f32 "
        "{%0,%1,%2,%3},{%4,%5,%6,%7},{%8,%9},{%0,%1,%2,%3};\n"
        : "+f"(c[0]), "+f"(c[1]), "+f"(c[2]), "+f"(c[3])
        : "r"(a0), "r"(a1), "r"(a2), "r"(a3), "r"(b0), "r"(b1));
}

__device__ __forceinline__ uint32_t pack_h2(float lo, float hi) {
    __half2 h = __floats2half2_rn(lo, hi);
    return *reinterpret_cast<uint32_t*>(&h);
}

__device__ __forceinline__ float swishf(float v) { return v / (1.f + __expf(-v)); }

// ============ Kernel 1: Q/K/V projections ============
#define PROJ_SMEM (3 * 16384 * 4 + 1024 * 4 + 64 * 130 * 2)

__global__ __launch_bounds__(256, 1)
void proj_kernel(const float* __restrict__ x,
                 const float* __restrict__ Wq,
                 const float* __restrict__ Wk,
                 const float* __restrict__ Wv) {
    extern __shared__ char smem[];
    float* sWq = (float*)smem;
    float* sWk = sWq + 16384;
    float* sWv = sWk + 16384;
    float* xs  = sWv + 16384;              // [8][128]
    __half* vbuf = (__half*)(xs + 1024);   // [64][130]

    const int tid = threadIdx.x;
    for (int i = tid; i < 16384; i += 256) {
        sWq[i] = Wq[i]; sWk[i] = Wk[i]; sWv[i] = Wv[i];
    }
    const int row0 = blockIdx.x * 64;
    const int b    = row0 >> 12;
    const int a0   = row0 & (NA - 1);
    const int d = tid & 127, h = tid >> 7;
    __syncthreads();

    for (int chunk = 0; chunk < 8; chunk++) {
        const int r0 = row0 + chunk * 8;
        *(float4*)(xs + tid * 4) = *(const float4*)(x + (size_t)r0 * ND + tid * 4);
        __syncthreads();
        float qa[4] = {0,0,0,0}, ka[4] = {0,0,0,0}, va[4] = {0,0,0,0};
        #pragma unroll 4
        for (int j = 0; j < 128; j++) {
            const float wq = sWq[j * 128 + d];
            const float wk = sWk[j * 128 + d];
            const float wv = sWv[j * 128 + d];
            #pragma unroll
            for (int rr = 0; rr < 4; rr++) {
                const float xv = xs[(h * 4 + rr) * 128 + j];
                qa[rr] = fmaf(xv, wq, qa[rr]);
                ka[rr] = fmaf(xv, wk, ka[rr]);
                va[rr] = fmaf(xv, wv, va[rr]);
            }
        }
        #pragma unroll
        for (int rr = 0; rr < 4; rr++) {
            const int grow = r0 + h * 4 + rr;
            g_Qh[(size_t)grow * ND + d] = __float2half_rn(qa[rr]);
            g_Kh[(size_t)grow * ND + d] = __float2half_rn(ka[rr]);
            vbuf[(chunk * 8 + h * 4 + rr) * 130 + d] = __float2half_rn(va[rr]);
        }
        __syncthreads();
    }
    const int c = tid & 63, dgrp = tid >> 6;   // dgrp 0..3
    #pragma unroll 4
    for (int k = 0; k < 32; k++) {
        const int dd = dgrp * 32 + k;
        g_Vt[((size_t)(b * ND + dd)) * NA + a0 + c] = vbuf[c * 130 + dd];
    }
}

// ============ Kernel 2: flash attention + connectivity bias ============
#define SQ_OFF 0
#define SK_OFF (128 * 136 * 2)
#define SV_OFF (SK_OFF + 64 * 136 * 2)
#define ATTN_SMEM (SV_OFF + 128 * 72 * 2)

__global__ __launch_bounds__(256, 1)
void attn_kernel(const float* __restrict__ conn) {
    extern __shared__ char smem[];
    __half* sQ = (__half*)(smem + SQ_OFF);  // [128][136]
    __half* sK = (__half*)(smem + SK_OFF);  // [64][136]
    __half* sV = (__half*)(smem + SV_OFF);  // [128][72] = Vt[d][key]

    const int tid = threadIdx.x;
    const int w = tid >> 5, lane = tid & 31;
    const int g = lane >> 2, t = lane & 3;
    const int b = blockIdx.y;
    const int q0 = blockIdx.x * 128;
    const int qw = w * 16;

    const __half* Qg = g_Qh + ((size_t)(b * NA + q0)) * ND;
    for (int i = tid; i < 2048; i += 256) {
        const int row = i >> 4, c8 = i & 15;
        *(uint4*)(sQ + row * 136 + c8 * 8) = *(const uint4*)(Qg + row * ND + c8 * 8);
    }
    __syncthreads();

    uint32_t qf[8][4];
    #pragma unroll
    for (int s = 0; s < 8; s++) {
        const __half* base = sQ + (qw + g) * 136 + 16 * s + 2 * t;
        qf[s][0] = *(const uint32_t*)(base);
        qf[s][1] = *(const uint32_t*)(base + 8 * 136);
        qf[s][2] = *(const uint32_t*)(base + 8);
        qf[s][3] = *(const uint32_t*)(base + 8 * 136 + 8);
    }

    float o[16][4];
    #pragma unroll
    for (int nt = 0; nt < 16; nt++) { o[nt][0]=o[nt][1]=o[nt][2]=o[nt][3]=0.f; }
    float m0 = -INFINITY, m1 = -INFINITY, l0 = 0.f, l1 = 0.f;

    const float* connR0 = conn + ((size_t)(b * NA + q0 + qw + g)) * NA;
    const float* connR1 = connR0 + (size_t)8 * NA;
    const __half* Kbase = g_Kh + ((size_t)(b * NA)) * ND;
    const __half* Vbase = g_Vt + ((size_t)(b * ND)) * NA;
    const float invs = 0.08838834764831845f;

    for (int kt = 0; kt < 64; kt++) {
        const int k0 = kt * 64;
        __syncthreads();
        const __half* Kg = Kbase + (size_t)k0 * ND;
        for (int i = tid; i < 1024; i += 256) {
            const int row = i >> 4, c8 = i & 15;
            *(uint4*)(sK + row * 136 + c8 * 8) = *(const uint4*)(Kg + row * ND + c8 * 8);
        }
        for (int i = tid; i < 1024; i += 256) {
            const int dd = i >> 3, c8 = i & 7;
            *(uint4*)(sV + dd * 72 + c8 * 8) = *(const uint4*)(Vbase + (size_t)dd * NA + k0 + c8 * 8);
        }
        float2 cf0[8], cf1[8];
        #pragma unroll
        for (int nt = 0; nt < 8; nt++) {
            cf0[nt] = *(const float2*)(connR0 + k0 + nt * 8 + 2 * t);
            cf1[nt] = *(const float2*)(connR1 + k0 + nt * 8 + 2 * t);
        }
        __syncthreads();

        float sacc[8][4];
        #pragma unroll
        for (int nt = 0; nt < 8; nt++) { sacc[nt][0]=sacc[nt][1]=sacc[nt][2]=sacc[nt][3]=0.f; }
        #pragma unroll
        for (int s = 0; s < 8; s++) {
            #pragma unroll
            for (int nt = 0; nt < 8; nt++) {
                const __half* kb = sK + (nt * 8 + g) * 136 + 16 * s + 2 * t;
                const uint32_t b0 = *(const uint32_t*)kb;
                const uint32_t b1 = *(const uint32_t*)(kb + 8);
                mma_f16(sacc[nt], qf[s][0], qf[s][1], qf[s][2], qf[s][3], b0, b1);
            }
        }
        float mt0 = -INFINITY, mt1 = -INFINITY;
        #pragma unroll
        for (int nt = 0; nt < 8; nt++) {
            sacc[nt][0] = fmaf(sacc[nt][0], invs, cf0[nt].x);
            sacc[nt][1] = fmaf(sacc[nt][1], invs, cf0[nt].y);
            sacc[nt][2] = fmaf(sacc[nt][2], invs, cf1[nt].x);
            sacc[nt][3] = fmaf(sacc[nt][3], invs, cf1[nt].y);
            mt0 = fmaxf(mt0, fmaxf(sacc[nt][0], sacc[nt][1]));
            mt1 = fmaxf(mt1, fmaxf(sacc[nt][2], sacc[nt][3]));
        }
        mt0 = fmaxf(mt0, __shfl_xor_sync(0xffffffffu, mt0, 1));
        mt0 = fmaxf(mt0, __shfl_xor_sync(0xffffffffu, mt0, 2));
        mt1 = fmaxf(mt1, __shfl_xor_sync(0xffffffffu, mt1, 1));
        mt1 = fmaxf(mt1, __shfl_xor_sync(0xffffffffu, mt1, 2));
        const float mn0 = fmaxf(m0, mt0), mn1 = fmaxf(m1, mt1);
        const float f0 = __expf(m0 - mn0), f1 = __expf(m1 - mn1);
        m0 = mn0; m1 = mn1;
        float s0 = 0.f, s1 = 0.f;
        #pragma unroll
        for (int nt = 0; nt < 8; nt++) {
            sacc[nt][0] = __expf(sacc[nt][0] - mn0);
            sacc[nt][1] = __expf(sacc[nt][1] - mn0);
            sacc[nt][2] = __expf(sacc[nt][2] - mn1);
            sacc[nt][3] = __expf(sacc[nt][3] - mn1);
            s0 += sacc[nt][0] + sacc[nt][1];
            s1 += sacc[nt][2] + sacc[nt][3];
        }
        s0 += __shfl_xor_sync(0xffffffffu, s0, 1);
        s0 += __shfl_xor_sync(0xffffffffu, s0, 2);
        s1 += __shfl_xor_sync(0xffffffffu, s1, 1);
        s1 += __shfl_xor_sync(0xffffffffu, s1, 2);
        l0 = l0 * f0 + s0;
        l1 = l1 * f1 + s1;
        #pragma unroll
        for (int nt = 0; nt < 16; nt++) {
            o[nt][0] *= f0; o[nt][1] *= f0; o[nt][2] *= f1; o[nt][3] *= f1;
        }
        #pragma unroll
        for (int kk = 0; kk < 4; kk++) {
            const uint32_t a0 = pack_h2(sacc[2*kk][0],   sacc[2*kk][1]);
            const uint32_t a1 = pack_h2(sacc[2*kk][2],   sacc[2*kk][3]);
            const uint32_t a2 = pack_h2(sacc[2*kk+1][0], sacc[2*kk+1][1]);
            const uint32_t a3 = pack_h2(sacc[2*kk+1][2], sacc[2*kk+1][3]);
            #pragma unroll
            for (int nt = 0; nt < 16; nt++) {
                const __half* vb = sV + (nt * 8 + g) * 72 + 16 * kk + 2 * t;
                const uint32_t b0 = *(const uint32_t*)vb;
                const uint32_t b1 = *(const uint32_t*)(vb + 8);
                mma_f16(o[nt], a0, a1, a2, a3, b0, b1);
            }
        }
    }
    const float r0 = 1.f / l0, r1 = 1.f / l1;
    float* H0 = g_H + ((size_t)(b * NA + q0 + qw + g)) * ND;
    float* H1 = H0 + 8 * ND;
    #pragma unroll
    for (int nt = 0; nt < 16; nt++) {
        *(float2*)(H0 + nt * 8 + 2 * t) = make_float2(o[nt][0] * r0, o[nt][1] * r0);
        *(float2*)(H1 + nt * 8 + 2 * t) = make_float2(o[nt][2] * r1, o[nt][3] * r1);
    }
}

// ============ Kernel 3: swish -> W1 -> swish -> W2 -> LayerNorm ============
#define MLP_SMEM (2 * 16384 * 4 + 2 * 1024 * 4)

__global__ __launch_bounds__(256, 1)
void mlp_kernel(const float* __restrict__ W1, const float* __restrict__ b1,
                const float* __restrict__ W2, const float* __restrict__ b2,
                const float* __restrict__ gamma, const float* __restrict__ beta,
                float* __restrict__ out) {
    extern __shared__ char smem[];
    float* sW1 = (float*)smem;
    float* sW2 = sW1 + 16384;
    float* s1  = sW2 + 16384;   // [8][128]
    float* s2  = s1 + 1024;     // [8][128]

    const int tid = threadIdx.x;
    for (int i = tid; i < 16384; i += 256) { sW1[i] = W1[i]; sW2[i] = W2[i]; }
    const int row0 = blockIdx.x * 64;
    const int d = tid & 127, h = tid >> 7;
    const float bb1 = b1[d], bb2 = b2[d];
    __syncthreads();

    for (int chunk = 0; chunk < 8; chunk++) {
        const int r0 = row0 + chunk * 8;
        {
            float4 v = *(const float4*)(g_H + (size_t)r0 * ND + tid * 4);
            *(float4*)(s1 + tid * 4) =
                make_float4(swishf(v.x), swishf(v.y), swishf(v.z), swishf(v.w));
        }
        __syncthreads();
        float acc[4] = {0,0,0,0};
        #pragma unroll 4
        for (int j = 0; j < 128; j++) {
            const float wv = sW1[j * 128 + d];
            #pragma unroll
            for (int rr = 0; rr < 4; rr++)
                acc[rr] = fmaf(s1[(h * 4 + rr) * 128 + j], wv, acc[rr]);
        }
        #pragma unroll
        for (int rr = 0; rr < 4; rr++)
            s2[(h * 4 + rr) * 128 + d] = swishf(acc[rr] + bb1);
        __syncthreads();
        float a2[4] = {0,0,0,0};
        #pragma unroll 4
        for (int j = 0; j < 128; j++) {
            const float wv = sW2[j * 128 + d];
            #pragma unroll
            for (int rr = 0; rr < 4; rr++)
                a2[rr] = fmaf(s2[(h * 4 + rr) * 128 + j], wv, a2[rr]);
        }
        #pragma unroll
        for (int rr = 0; rr < 4; rr++)
            s1[(h * 4 + rr) * 128 + d] = a2[rr] + bb2;
        __syncthreads();
        {
            const int lane = tid & 31, wr = tid >> 5;   // warp wr owns row wr
            float sum = 0.f, sq = 0.f;
            #pragma unroll
            for (int k = lane; k < 128; k += 32) {
                const float v = s1[wr * 128 + k];
                sum += v; sq += v * v;
            }
            #pragma unroll
            for (int off = 16; off; off >>= 1) {
                sum += __shfl_xor_sync(0xffffffffu, sum, off);
                sq  += __shfl_xor_sync(0xffffffffu, sq,  off);
            }
            const float mu = sum * 0.0078125f;
            const float var = sq * 0.0078125f - mu * mu;
            const float rstd = rsqrtf(var + 1e-5f);
            #pragma unroll
            for (int k = lane; k < 128; k += 32) {
                const float v = (s1[wr * 128 + k] - mu) * rstd;
                out[(size_t)(r0 + wr) * ND + k] = fmaf(v, gamma[k], beta[k]);
            }
        }
        __syncthreads();
    }
}

extern "C" void kernel_launch(void* const* d_in, const int* in_sizes, int n_in,
                              void* d_out, int out_size) {
    const float* x     = (const float*)d_in[0];
    const float* conn  = (const float*)d_in[1];
    const float* Wq    = (const float*)d_in[2];
    const float* Wk    = (const float*)d_in[3];
    const float* Wv    = (const float*)d_in[4];
    const float* W1    = (const float*)d_in[5];
    const float* b1    = (const float*)d_in[6];
    const float* W2    = (const float*)d_in[7];
    const float* b2    = (const float*)d_in[8];
    const float* gamma = (const float*)d_in[9];
    const float* beta  = (const float*)d_in[10];
    float* out = (float*)d_out;

    static bool attr_done = false;
    if (!attr_done) {
        cudaFuncSetAttribute(proj_kernel, cudaFuncAttributeMaxDynamicSharedMemorySize, PROJ_SMEM);
        cudaFuncSetAttribute(attn_kernel, cudaFuncAttributeMaxDynamicSharedMemorySize, ATTN_SMEM);
        cudaFuncSetAttribute(mlp_kernel,  cudaFuncAttributeMaxDynamicSharedMemorySize, MLP_SMEM);
        attr_done = true;
    }

    proj_kernel<<<256, 256, PROJ_SMEM>>>(x, Wq, Wk, Wv);
    attn_kernel<<<dim3(32, 4), 256, ATTN_SMEM>>>(conn);
    mlp_kernel<<<256, 256, MLP_SMEM>>>(W1, b1, W2, b2, gamma, beta, out);
}

// round 4
// speedup vs baseline: 1.9493x; 1.9493x over previous
#include <cuda_runtime.h>
#include <cuda_fp16.h>
#include <cstdint>

#define NB 4
#define NA 4096
#define ND 128

__device__ __half g_Qh[NB * NA * ND];
__device__ __half g_Kh[NB * NA * ND];
__device__ __half g_Vt[NB * ND * NA];   // [b][d][a]
__device__ float  g_H [NB * NA * ND];

// ======================= helpers =======================
__device__ __forceinline__ uint32_t smem_u32(const void* p) {
    uint32_t a;
    asm("{ .reg .u64 t; cvta.to.shared.u64 t, %1; cvt.u32.u64 %0, t; }" : "=r"(a) : "l"(p));
    return a;
}
__device__ __forceinline__ void mma_f16(float c[4],
                                        uint32_t a0, uint32_t a1, uint32_t a2, uint32_t a3,
                                        uint32_t b0, uint32_t b1) {
    asm volatile(
        "mma.sync.aligned.m16n8k16.row.col.f32.f16.f16.f32 "
        "{%0,%1,%2,%3},{%4,%5,%6,%7},{%8,%9},{%0,%1,%2,%3};\n"
        : "+f"(c[0]), "+f"(c[1]), "+f"(c[2]), "+f"(c[3])
        : "r"(a0), "r"(a1), "r"(a2), "r"(a3), "r"(b0), "r"(b1));
}
__device__ __forceinline__ void ldsm_x4(uint32_t& r0, uint32_t& r1, uint32_t& r2, uint32_t& r3,
                                        uint32_t addr) {
    asm volatile("ldmatrix.sync.aligned.m8n8.x4.shared.b16 {%0,%1,%2,%3}, [%4];"
                 : "=r"(r0), "=r"(r1), "=r"(r2), "=r"(r3) : "r"(addr));
}
__device__ __forceinline__ void cpa16(uint32_t dst, const void* src) {
    asm volatile("cp.async.cg.shared.global [%0], [%1], 16;" :: "r"(dst), "l"(src) : "memory");
}
#define CP_COMMIT() asm volatile("cp.async.commit_group;" ::: "memory")
#define CP_WAIT1()  asm volatile("cp.async.wait_group 1;" ::: "memory")

__device__ __forceinline__ float ex2f(float x) {
    float y; asm("ex2.approx.ftz.f32 %0, %1;" : "=f"(y) : "f"(x)); return y;
}
__device__ __forceinline__ uint32_t pack_h2(float lo, float hi) {
    __half2 h = __floats2half2_rn(lo, hi);
    return *reinterpret_cast<uint32_t*>(&h);
}
__device__ __forceinline__ float swishf(float v) { return v / (1.f + __expf(-v)); }

// ======================= Kernel 1: projections =======================
#define PROJ_SMEM (3 * 16384 * 4 + 1024 * 4 + 64 * 130 * 2)

__global__ __launch_bounds__(256, 1)
void proj_kernel(const float* __restrict__ x,
                 const float* __restrict__ Wq,
                 const float* __restrict__ Wk,
                 const float* __restrict__ Wv) {
    extern __shared__ char smem[];
    float* sWq = (float*)smem;
    float* sWk = sWq + 16384;
    float* sWv = sWk + 16384;
    float* xs  = sWv + 16384;
    __half* vbuf = (__half*)(xs + 1024);

    const int tid = threadIdx.x;
    for (int i = tid; i < 16384; i += 256) {
        sWq[i] = Wq[i]; sWk[i] = Wk[i]; sWv[i] = Wv[i];
    }
    const int row0 = blockIdx.x * 64;
    const int b    = row0 >> 12;
    const int a0   = row0 & (NA - 1);
    const int d = tid & 127, h = tid >> 7;
    __syncthreads();

    for (int chunk = 0; chunk < 8; chunk++) {
        const int r0 = row0 + chunk * 8;
        *(float4*)(xs + tid * 4) = *(const float4*)(x + (size_t)r0 * ND + tid * 4);
        __syncthreads();
        float qa[4] = {0,0,0,0}, ka[4] = {0,0,0,0}, va[4] = {0,0,0,0};
        #pragma unroll 2
        for (int j0 = 0; j0 < 128; j0 += 4) {
            float xa[4][4];
            #pragma unroll
            for (int rr = 0; rr < 4; rr++) {
                float4 v = *(const float4*)&xs[(h * 4 + rr) * 128 + j0];
                xa[rr][0] = v.x; xa[rr][1] = v.y; xa[rr][2] = v.z; xa[rr][3] = v.w;
            }
            #pragma unroll
            for (int jj = 0; jj < 4; jj++) {
                const float wq = sWq[(j0 + jj) * 128 + d];
                const float wk = sWk[(j0 + jj) * 128 + d];
                const float wv = sWv[(j0 + jj) * 128 + d];
                #pragma unroll
                for (int rr = 0; rr < 4; rr++) {
                    qa[rr] = fmaf(xa[rr][jj], wq, qa[rr]);
                    ka[rr] = fmaf(xa[rr][jj], wk, ka[rr]);
                    va[rr] = fmaf(xa[rr][jj], wv, va[rr]);
                }
            }
        }
        #pragma unroll
        for (int rr = 0; rr < 4; rr++) {
            const int grow = r0 + h * 4 + rr;
            g_Qh[(size_t)grow * ND + d] = __float2half_rn(qa[rr]);
            g_Kh[(size_t)grow * ND + d] = __float2half_rn(ka[rr]);
            vbuf[(chunk * 8 + h * 4 + rr) * 130 + d] = __float2half_rn(va[rr]);
        }
        __syncthreads();
    }
    const int c = tid & 63, dgrp = tid >> 6;
    #pragma unroll 4
    for (int k = 0; k < 32; k++) {
        const int dd = dgrp * 32 + k;
        g_Vt[((size_t)(b * ND + dd)) * NA + a0 + c] = vbuf[c * 130 + dd];
    }
}

// ======================= Kernel 2: flash attention (legacy mma, pipelined) =======================
// smem layout (bytes):
#define SM_Q  0                       // 128 x 272B  (136 halves/row)
#define SM_K0 34816                   // 64 x 272B
#define SM_K1 (SM_K0 + 17408)
#define SM_V0 (SM_K1 + 17408)         // 128 x 144B  (72 halves/row)
#define SM_V1 (SM_V0 + 18432)
#define SM_C0 (SM_V1 + 18432)         // 128 x 272B  (68 floats/row)
#define SM_C1 (SM_C0 + 34816)
#define ATTN_SMEM (SM_C1 + 34816)     // 176128

__device__ __forceinline__ void load_tile(uint32_t sb, int kbuf, int vbuf, int cbuf,
                                          int b, int q0, int k0, int tid,
                                          const float* __restrict__ conn) {
    const __half* Kg = g_Kh + ((size_t)(b * NA + k0)) * ND;
    #pragma unroll
    for (int i = tid; i < 1024; i += 256) {
        const int r = i >> 4, c = i & 15;
        cpa16(sb + (uint32_t)(kbuf + r * 272 + c * 16), Kg + r * ND + c * 8);
    }
    const __half* Vg = g_Vt + ((size_t)(b * ND)) * NA + k0;
    #pragma unroll
    for (int i = tid; i < 1024; i += 256) {
        const int r = i >> 3, c = i & 7;
        cpa16(sb + (uint32_t)(vbuf + r * 144 + c * 16), Vg + (size_t)r * NA + c * 8);
    }
    const float* Cg = conn + ((size_t)(b * NA + q0)) * NA + k0;
    #pragma unroll
    for (int i = tid; i < 2048; i += 256) {
        const int r = i >> 4, c = i & 15;
        cpa16(sb + (uint32_t)(cbuf + r * 272 + c * 16), Cg + (size_t)r * NA + c * 4);
    }
}

__global__ __launch_bounds__(256, 1)
void attn_kernel(const float* __restrict__ conn) {
    extern __shared__ __align__(16) char smem[];
    const uint32_t sb = smem_u32(smem);
    const int tid = threadIdx.x;
    const int w = tid >> 5, lane = tid & 31;
    const int g = lane >> 2, t = lane & 3;
    const int b = blockIdx.y;
    const int q0 = blockIdx.x * 128;
    const int qw = w * 16;

    // ldmatrix lane-address components
    const int r_l = ((lane & 16) >> 1) + (lane & 7);   // row within 16-row pair-block
    const int c_l = (lane & 8);                        // +8 halves for b1 matrices

    // ---- stage Q + tile0 (group0), tile1 (group1) ----
    {
        const __half* Qg = g_Qh + ((size_t)(b * NA + q0)) * ND;
        #pragma unroll
        for (int i = tid; i < 2048; i += 256) {
            const int r = i >> 4, c = i & 15;
            cpa16(sb + (uint32_t)(SM_Q + r * 272 + c * 16), Qg + r * ND + c * 8);
        }
    }
    load_tile(sb, SM_K0, SM_V0, SM_C0, b, q0, 0, tid, conn);
    CP_COMMIT();
    load_tile(sb, SM_K1, SM_V1, SM_C1, b, q0, 64, tid, conn);
    CP_COMMIT();

    CP_WAIT1();            // group0 (Q + tile0) complete
    __syncthreads();

    // ---- Q fragments, register-resident for all 64 tiles ----
    uint32_t qf[8][4];
    #pragma unroll
    for (int s = 0; s < 8; s++) {
        const char* base = smem + SM_Q + (qw + g) * 272 + (16 * s + 2 * t) * 2;
        qf[s][0] = *(const uint32_t*)(base);
        qf[s][1] = *(const uint32_t*)(base + 8 * 272);
        qf[s][2] = *(const uint32_t*)(base + 16);
        qf[s][3] = *(const uint32_t*)(base + 8 * 272 + 16);
    }

    float o[16][4];
    #pragma unroll
    for (int nt = 0; nt < 16; nt++) { o[nt][0]=o[nt][1]=o[nt][2]=o[nt][3]=0.f; }
    float l0 = 0.f, l1 = 0.f;

    const float K1c = 0.08838834764831845f * 1.44269504088896340f;  // invs * log2(e)
    const float K2c = 1.44269504088896340f;

    for (int kt = 0; kt < 64; kt++) {
        const int kbuf = (kt & 1) ? SM_K1 : SM_K0;
        const int vbuf = (kt & 1) ? SM_V1 : SM_V0;
        const int cbuf = (kt & 1) ? SM_C1 : SM_C0;
        CP_WAIT1();
        __syncthreads();

        // ---- S = Q K^T ----
        float sacc[8][4];
        #pragma unroll
        for (int nt = 0; nt < 8; nt++) { sacc[nt][0]=sacc[nt][1]=sacc[nt][2]=sacc[nt][3]=0.f; }
        #pragma unroll
        for (int s = 0; s < 8; s++) {
            #pragma unroll
            for (int p = 0; p < 4; p++) {
                uint32_t b0, b1, b2, b3;
                const uint32_t ka = sb + (uint32_t)(kbuf + (p * 16 + r_l) * 272 + (16 * s + c_l) * 2);
                ldsm_x4(b0, b1, b2, b3, ka);
                mma_f16(sacc[2 * p],     qf[s][0], qf[s][1], qf[s][2], qf[s][3], b0, b1);
                mma_f16(sacc[2 * p + 1], qf[s][0], qf[s][1], qf[s][2], qf[s][3], b2, b3);
            }
        }

        // ---- p = 2^(s*invs*log2e + conn*log2e), no-max softmax ----
        const float* c0p = (const float*)(smem + cbuf) + (qw + g) * 68 + 2 * t;
        const float* c1p = c0p + 8 * 68;
        #pragma unroll
        for (int nt = 0; nt < 8; nt++) {
            const float2 v0 = *(const float2*)(c0p + nt * 8);
            const float2 v1 = *(const float2*)(c1p + nt * 8);
            sacc[nt][0] = ex2f(fmaf(sacc[nt][0], K1c, v0.x * K2c));
            sacc[nt][1] = ex2f(fmaf(sacc[nt][1], K1c, v0.y * K2c));
            sacc[nt][2] = ex2f(fmaf(sacc[nt][2], K1c, v1.x * K2c));
            sacc[nt][3] = ex2f(fmaf(sacc[nt][3], K1c, v1.y * K2c));
            l0 += sacc[nt][0] + sacc[nt][1];
            l1 += sacc[nt][2] + sacc[nt][3];
        }

        // ---- O += P V ----
        #pragma unroll
        for (int kk = 0; kk < 4; kk++) {
            const uint32_t a0 = pack_h2(sacc[2*kk][0],   sacc[2*kk][1]);
            const uint32_t a1 = pack_h2(sacc[2*kk][2],   sacc[2*kk][3]);
            const uint32_t a2 = pack_h2(sacc[2*kk+1][0], sacc[2*kk+1][1]);
            const uint32_t a3 = pack_h2(sacc[2*kk+1][2], sacc[2*kk+1][3]);
            #pragma unroll
            for (int p = 0; p < 8; p++) {
                uint32_t b0, b1, b2, b3;
                const uint32_t va = sb + (uint32_t)(vbuf + (p * 16 + r_l) * 144 + (16 * kk + c_l) * 2);
                ldsm_x4(b0, b1, b2, b3, va);
                mma_f16(o[2 * p],     a0, a1, a2, a3, b0, b1);
                mma_f16(o[2 * p + 1], a0, a1, a2, a3, b2, b3);
            }
        }

        __syncthreads();
        if (kt + 2 < 64) {
            load_tile(sb, kbuf, vbuf, cbuf, b, q0, (kt + 2) * 64, tid, conn);
        }
        CP_COMMIT();
    }

    // ---- finalize: reduce l over key-quads, scale, store ----
    l0 += __shfl_xor_sync(0xffffffffu, l0, 1);
    l0 += __shfl_xor_sync(0xffffffffu, l0, 2);
    l1 += __shfl_xor_sync(0xffffffffu, l1, 1);
    l1 += __shfl_xor_sync(0xffffffffu, l1, 2);
    const float r0 = 1.f / l0, r1 = 1.f / l1;
    float* H0 = g_H + ((size_t)(b * NA + q0 + qw + g)) * ND;
    float* H1 = H0 + 8 * ND;
    #pragma unroll
    for (int nt = 0; nt < 16; nt++) {
        *(float2*)(H0 + nt * 8 + 2 * t) = make_float2(o[nt][0] * r0, o[nt][1] * r0);
        *(float2*)(H1 + nt * 8 + 2 * t) = make_float2(o[nt][2] * r1, o[nt][3] * r1);
    }
}

// ======================= Kernel 3: MLP tail =======================
#define MLP_SMEM (2 * 16384 * 4 + 2 * 1024 * 4)

__global__ __launch_bounds__(256, 1)
void mlp_kernel(const float* __restrict__ W1, const float* __restrict__ b1,
                const float* __restrict__ W2, const float* __restrict__ b2,
                const float* __restrict__ gamma, const float* __restrict__ beta,
                float* __restrict__ out) {
    extern __shared__ char smem[];
    float* sW1 = (float*)smem;
    float* sW2 = sW1 + 16384;
    float* s1  = sW2 + 16384;
    float* s2  = s1 + 1024;

    const int tid = threadIdx.x;
    for (int i = tid; i < 16384; i += 256) { sW1[i] = W1[i]; sW2[i] = W2[i]; }
    const int row0 = blockIdx.x * 64;
    const int d = tid & 127, h = tid >> 7;
    const float bb1 = b1[d], bb2 = b2[d];
    __syncthreads();

    for (int chunk = 0; chunk < 8; chunk++) {
        const int r0 = row0 + chunk * 8;
        {
            float4 v = *(const float4*)(g_H + (size_t)r0 * ND + tid * 4);
            *(float4*)(s1 + tid * 4) =
                make_float4(swishf(v.x), swishf(v.y), swishf(v.z), swishf(v.w));
        }
        __syncthreads();
        float acc[4] = {0,0,0,0};
        #pragma unroll 2
        for (int j0 = 0; j0 < 128; j0 += 4) {
            float xa[4][4];
            #pragma unroll
            for (int rr = 0; rr < 4; rr++) {
                float4 v = *(const float4*)&s1[(h * 4 + rr) * 128 + j0];
                xa[rr][0] = v.x; xa[rr][1] = v.y; xa[rr][2] = v.z; xa[rr][3] = v.w;
            }
            #pragma unroll
            for (int jj = 0; jj < 4; jj++) {
                const float wv = sW1[(j0 + jj) * 128 + d];
                #pragma unroll
                for (int rr = 0; rr < 4; rr++)
                    acc[rr] = fmaf(xa[rr][jj], wv, acc[rr]);
            }
        }
        #pragma unroll
        for (int rr = 0; rr < 4; rr++)
            s2[(h * 4 + rr) * 128 + d] = swishf(acc[rr] + bb1);
        __syncthreads();
        float a2[4] = {0,0,0,0};
        #pragma unroll 2
        for (int j0 = 0; j0 < 128; j0 += 4) {
            float xa[4][4];
            #pragma unroll
            for (int rr = 0; rr < 4; rr++) {
                float4 v = *(const float4*)&s2[(h * 4 + rr) * 128 + j0];
                xa[rr][0] = v.x; xa[rr][1] = v.y; xa[rr][2] = v.z; xa[rr][3] = v.w;
            }
            #pragma unroll
            for (int jj = 0; jj < 4; jj++) {
                const float wv = sW2[(j0 + jj) * 128 + d];
                #pragma unroll
                for (int rr = 0; rr < 4; rr++)
                    a2[rr] = fmaf(xa[rr][jj], wv, a2[rr]);
            }
        }
        #pragma unroll
        for (int rr = 0; rr < 4; rr++)
            s1[(h * 4 + rr) * 128 + d] = a2[rr] + bb2;
        __syncthreads();
        {
            const int lane = tid & 31, wr = tid >> 5;
            float sum = 0.f, sq = 0.f;
            #pragma unroll
            for (int k = lane; k < 128; k += 32) {
                const float v = s1[wr * 128 + k];
                sum += v; sq += v * v;
            }
            #pragma unroll
            for (int off = 16; off; off >>= 1) {
                sum += __shfl_xor_sync(0xffffffffu, sum, off);
                sq  += __shfl_xor_sync(0xffffffffu, sq,  off);
            }
            const float mu = sum * 0.0078125f;
            const float var = sq * 0.0078125f - mu * mu;
            const float rstd = rsqrtf(var + 1e-5f);
            #pragma unroll
            for (int k = lane; k < 128; k += 32) {
                const float v = (s1[wr * 128 + k] - mu) * rstd;
                out[(size_t)(r0 + wr) * ND + k] = fmaf(v, gamma[k], beta[k]);
            }
        }
        __syncthreads();
    }
}

extern "C" void kernel_launch(void* const* d_in, const int* in_sizes, int n_in,
                              void* d_out, int out_size) {
    const float* x     = (const float*)d_in[0];
    const float* conn  = (const float*)d_in[1];
    const float* Wq    = (const float*)d_in[2];
    const float* Wk    = (const float*)d_in[3];
    const float* Wv    = (const float*)d_in[4];
    const float* W1    = (const float*)d_in[5];
    const float* b1    = (const float*)d_in[6];
    const float* W2    = (const float*)d_in[7];
    const float* b2    = (const float*)d_in[8];
    const float* gamma = (const float*)d_in[9];
    const float* beta  = (const float*)d_in[10];
    float* out = (float*)d_out;

    static bool attr_done = false;
    if (!attr_done) {
        cudaFuncSetAttribute(proj_kernel, cudaFuncAttributeMaxDynamicSharedMemorySize, PROJ_SMEM);
        cudaFuncSetAttribute(attn_kernel, cudaFuncAttributeMaxDynamicSharedMemorySize, ATTN_SMEM);
        cudaFuncSetAttribute(mlp_kernel,  cudaFuncAttributeMaxDynamicSharedMemorySize, MLP_SMEM);
        attr_done = true;
    }

    proj_kernel<<<256, 256, PROJ_SMEM>>>(x, Wq, Wk, Wv);
    attn_kernel<<<dim3(32, 4), 256, ATTN_SMEM>>>(conn);
    mlp_kernel<<<256, 256, MLP_SMEM>>>(W1, b1, W2, b2, gamma, beta, out);
}

// round 5
// speedup vs baseline: 2.8500x; 1.4620x over previous
#include <cuda_runtime.h>
#include <cuda_fp16.h>
#include <cstdint>

#define NB 4
#define NA 4096
#define ND 128

__device__ __half g_Qh[NB * NA * ND];
__device__ __half g_Kh[NB * NA * ND];
__device__ __half g_Vt[NB * ND * NA];   // [b][d][a]
__device__ float  g_H [NB * NA * ND];

// ======================= helpers =======================
__device__ __forceinline__ uint32_t smem_u32(const void* p) {
    uint32_t a;
    asm("{ .reg .u64 t; cvta.to.shared.u64 t, %1; cvt.u32.u64 %0, t; }" : "=r"(a) : "l"(p));
    return a;
}
__device__ __forceinline__ void mma_f16(float c[4],
                                        uint32_t a0, uint32_t a1, uint32_t a2, uint32_t a3,
                                        uint32_t b0, uint32_t b1) {
    asm volatile(
        "mma.sync.aligned.m16n8k16.row.col.f32.f16.f16.f32 "
        "{%0,%1,%2,%3},{%4,%5,%6,%7},{%8,%9},{%0,%1,%2,%3};\n"
        : "+f"(c[0]), "+f"(c[1]), "+f"(c[2]), "+f"(c[3])
        : "r"(a0), "r"(a1), "r"(a2), "r"(a3), "r"(b0), "r"(b1));
}
__device__ __forceinline__ void ldsm_x4(uint32_t& r0, uint32_t& r1, uint32_t& r2, uint32_t& r3,
                                        uint32_t addr) {
    asm volatile("ldmatrix.sync.aligned.m8n8.x4.shared.b16 {%0,%1,%2,%3}, [%4];"
                 : "=r"(r0), "=r"(r1), "=r"(r2), "=r"(r3) : "r"(addr));
}
__device__ __forceinline__ void cpa16(uint32_t dst, const void* src) {
    asm volatile("cp.async.cg.shared.global [%0], [%1], 16;" :: "r"(dst), "l"(src) : "memory");
}
#define CP_COMMIT() asm volatile("cp.async.commit_group;" ::: "memory")
#define CP_WAIT1()  asm volatile("cp.async.wait_group 1;" ::: "memory")

__device__ __forceinline__ float ex2f(float x) {
    float y; asm("ex2.approx.ftz.f32 %0, %1;" : "=f"(y) : "f"(x)); return y;
}
__device__ __forceinline__ uint32_t pack_h2(float lo, float hi) {
    __half2 h = __floats2half2_rn(lo, hi);
    return *reinterpret_cast<uint32_t*>(&h);
}
__device__ __forceinline__ float swishf(float v) { return v / (1.f + __expf(-v)); }

// transpose-load a 128x128 fp32 weight W[k][n] into smem half [n][k], 272B row stride
__device__ __forceinline__ void load_wt(__half* dst, const float* __restrict__ W, int tid) {
    #pragma unroll 4
    for (int it = 0; it < 64; it++) {
        const int i = tid + it * 256;
        const int k = i >> 7, n = i & 127;
        dst[n * 136 + k] = __float2half_rn(W[i]);
    }
}

// ======================= Kernel 1: projections via mma =======================
// smem: sX[128][136h] @0, sWt_q @34816, sWt_k @69632, sWt_v @104448, sVst @139264
#define PROJ_SMEM (5 * 34816)

__global__ __launch_bounds__(256, 1)
void proj_kernel(const float* __restrict__ x,
                 const float* __restrict__ Wq,
                 const float* __restrict__ Wk,
                 const float* __restrict__ Wv) {
    extern __shared__ __align__(16) char smem[];
    const uint32_t sb = smem_u32(smem);
    const int tid = threadIdx.x;
    const int w = tid >> 5, lane = tid & 31;
    const int g = lane >> 2, t = lane & 3;
    const int r_l = ((lane & 16) >> 1) + (lane & 7);
    const int c_l = (lane & 8);
    const int row0 = blockIdx.x * 128;
    const int b = row0 >> 12, a0 = row0 & (NA - 1);
    const int qw = w * 16;

    __half* sX   = (__half*)smem;
    __half* sVst = (__half*)(smem + 139264);

    // x -> fp16 smem
    #pragma unroll 4
    for (int it = 0; it < 16; it++) {
        const int i = tid + it * 256;
        const int r = i >> 5, c4 = (i & 31) * 4;
        const float4 v = *(const float4*)(x + (size_t)(row0 + r) * ND + c4);
        uint2 u;
        u.x = pack_h2(v.x, v.y);
        u.y = pack_h2(v.z, v.w);
        *(uint2*)((char*)smem + r * 272 + c4 * 2) = u;
    }
    load_wt((__half*)(smem + 34816),  Wq, tid);
    load_wt((__half*)(smem + 69632),  Wk, tid);
    load_wt((__half*)(smem + 104448), Wv, tid);
    __syncthreads();

    // A-fragments (16 rows per warp), register-resident
    uint32_t xf[8][4];
    #pragma unroll
    for (int s = 0; s < 8; s++) {
        const char* base = (const char*)smem + (qw + g) * 272 + (16 * s + 2 * t) * 2;
        xf[s][0] = *(const uint32_t*)(base);
        xf[s][1] = *(const uint32_t*)(base + 8 * 272);
        xf[s][2] = *(const uint32_t*)(base + 16);
        xf[s][3] = *(const uint32_t*)(base + 8 * 272 + 16);
    }

    const int gr0 = row0 + qw + g;
    #pragma unroll
    for (int m = 0; m < 3; m++) {
        const uint32_t wb = sb + 34816u * (1 + m);
        float o[16][4];
        #pragma unroll
        for (int nt = 0; nt < 16; nt++) { o[nt][0]=o[nt][1]=o[nt][2]=o[nt][3]=0.f; }
        #pragma unroll
        for (int s = 0; s < 8; s++) {
            #pragma unroll
            for (int p = 0; p < 8; p++) {
                uint32_t b0, b1, b2, b3;
                ldsm_x4(b0, b1, b2, b3, wb + (uint32_t)((p * 16 + r_l) * 272 + (16 * s + c_l) * 2));
                mma_f16(o[2 * p],     xf[s][0], xf[s][1], xf[s][2], xf[s][3], b0, b1);
                mma_f16(o[2 * p + 1], xf[s][0], xf[s][1], xf[s][2], xf[s][3], b2, b3);
            }
        }
        if (m < 2) {
            __half* dst = (m == 0) ? g_Qh : g_Kh;
            #pragma unroll
            for (int nt = 0; nt < 16; nt++) {
                *(uint32_t*)(dst + (size_t)gr0 * ND + nt * 8 + 2 * t)       = pack_h2(o[nt][0], o[nt][1]);
                *(uint32_t*)(dst + (size_t)(gr0 + 8) * ND + nt * 8 + 2 * t) = pack_h2(o[nt][2], o[nt][3]);
            }
        } else {
            #pragma unroll
            for (int nt = 0; nt < 16; nt++) {
                *(uint32_t*)((char*)sVst + (qw + g) * 272 + (nt * 8 + 2 * t) * 2)     = pack_h2(o[nt][0], o[nt][1]);
                *(uint32_t*)((char*)sVst + (qw + g + 8) * 272 + (nt * 8 + 2 * t) * 2) = pack_h2(o[nt][2], o[nt][3]);
            }
        }
    }
    __syncthreads();
    // transposed V store: g_Vt[b][d][a0+c]
    const int c = tid & 127, dgrp = tid >> 7;
    #pragma unroll 4
    for (int k = 0; k < 64; k++) {
        const int dd = dgrp * 64 + k;
        g_Vt[((size_t)(b * ND + dd)) * NA + a0 + c] = sVst[c * 136 + dd];
    }
}

// ======================= Kernel 2: flash attention (unchanged from R4) =======================
#define SM_Q  0
#define SM_K0 34816
#define SM_K1 (SM_K0 + 17408)
#define SM_V0 (SM_K1 + 17408)
#define SM_V1 (SM_V0 + 18432)
#define SM_C0 (SM_V1 + 18432)
#define SM_C1 (SM_C0 + 34816)
#define ATTN_SMEM (SM_C1 + 34816)

__device__ __forceinline__ void load_tile(uint32_t sb, int kbuf, int vbuf, int cbuf,
                                          int b, int q0, int k0, int tid,
                                          const float* __restrict__ conn) {
    const __half* Kg = g_Kh + ((size_t)(b * NA + k0)) * ND;
    #pragma unroll
    for (int i = tid; i < 1024; i += 256) {
        const int r = i >> 4, c = i & 15;
        cpa16(sb + (uint32_t)(kbuf + r * 272 + c * 16), Kg + r * ND + c * 8);
    }
    const __half* Vg = g_Vt + ((size_t)(b * ND)) * NA + k0;
    #pragma unroll
    for (int i = tid; i < 1024; i += 256) {
        const int r = i >> 3, c = i & 7;
        cpa16(sb + (uint32_t)(vbuf + r * 144 + c * 16), Vg + (size_t)r * NA + c * 8);
    }
    const float* Cg = conn + ((size_t)(b * NA + q0)) * NA + k0;
    #pragma unroll
    for (int i = tid; i < 2048; i += 256) {
        const int r = i >> 4, c = i & 15;
        cpa16(sb + (uint32_t)(cbuf + r * 272 + c * 16), Cg + (size_t)r * NA + c * 4);
    }
}

__global__ __launch_bounds__(256, 1)
void attn_kernel(const float* __restrict__ conn) {
    extern __shared__ __align__(16) char smem[];
    const uint32_t sb = smem_u32(smem);
    const int tid = threadIdx.x;
    const int w = tid >> 5, lane = tid & 31;
    const int g = lane >> 2, t = lane & 3;
    const int b = blockIdx.y;
    const int q0 = blockIdx.x * 128;
    const int qw = w * 16;
    const int r_l = ((lane & 16) >> 1) + (lane & 7);
    const int c_l = (lane & 8);

    {
        const __half* Qg = g_Qh + ((size_t)(b * NA + q0)) * ND;
        #pragma unroll
        for (int i = tid; i < 2048; i += 256) {
            const int r = i >> 4, c = i & 15;
            cpa16(sb + (uint32_t)(SM_Q + r * 272 + c * 16), Qg + r * ND + c * 8);
        }
    }
    load_tile(sb, SM_K0, SM_V0, SM_C0, b, q0, 0, tid, conn);
    CP_COMMIT();
    load_tile(sb, SM_K1, SM_V1, SM_C1, b, q0, 64, tid, conn);
    CP_COMMIT();

    CP_WAIT1();
    __syncthreads();

    uint32_t qf[8][4];
    #pragma unroll
    for (int s = 0; s < 8; s++) {
        const char* base = smem + SM_Q + (qw + g) * 272 + (16 * s + 2 * t) * 2;
        qf[s][0] = *(const uint32_t*)(base);
        qf[s][1] = *(const uint32_t*)(base + 8 * 272);
        qf[s][2] = *(const uint32_t*)(base + 16);
        qf[s][3] = *(const uint32_t*)(base + 8 * 272 + 16);
    }

    float o[16][4];
    #pragma unroll
    for (int nt = 0; nt < 16; nt++) { o[nt][0]=o[nt][1]=o[nt][2]=o[nt][3]=0.f; }
    float l0 = 0.f, l1 = 0.f;

    const float K1c = 0.08838834764831845f * 1.44269504088896340f;
    const float K2c = 1.44269504088896340f;

    for (int kt = 0; kt < 64; kt++) {
        const int kbuf = (kt & 1) ? SM_K1 : SM_K0;
        const int vbuf = (kt & 1) ? SM_V1 : SM_V0;
        const int cbuf = (kt & 1) ? SM_C1 : SM_C0;
        CP_WAIT1();
        __syncthreads();

        float sacc[8][4];
        #pragma unroll
        for (int nt = 0; nt < 8; nt++) { sacc[nt][0]=sacc[nt][1]=sacc[nt][2]=sacc[nt][3]=0.f; }
        #pragma unroll
        for (int s = 0; s < 8; s++) {
            #pragma unroll
            for (int p = 0; p < 4; p++) {
                uint32_t b0, b1, b2, b3;
                const uint32_t ka = sb + (uint32_t)(kbuf + (p * 16 + r_l) * 272 + (16 * s + c_l) * 2);
                ldsm_x4(b0, b1, b2, b3, ka);
                mma_f16(sacc[2 * p],     qf[s][0], qf[s][1], qf[s][2], qf[s][3], b0, b1);
                mma_f16(sacc[2 * p + 1], qf[s][0], qf[s][1], qf[s][2], qf[s][3], b2, b3);
            }
        }

        const float* c0p = (const float*)(smem + cbuf) + (qw + g) * 68 + 2 * t;
        const float* c1p = c0p + 8 * 68;
        #pragma unroll
        for (int nt = 0; nt < 8; nt++) {
            const float2 v0 = *(const float2*)(c0p + nt * 8);
            const float2 v1 = *(const float2*)(c1p + nt * 8);
            sacc[nt][0] = ex2f(fmaf(sacc[nt][0], K1c, v0.x * K2c));
            sacc[nt][1] = ex2f(fmaf(sacc[nt][1], K1c, v0.y * K2c));
            sacc[nt][2] = ex2f(fmaf(sacc[nt][2], K1c, v1.x * K2c));
            sacc[nt][3] = ex2f(fmaf(sacc[nt][3], K1c, v1.y * K2c));
            l0 += sacc[nt][0] + sacc[nt][1];
            l1 += sacc[nt][2] + sacc[nt][3];
        }

        #pragma unroll
        for (int kk = 0; kk < 4; kk++) {
            const uint32_t a0 = pack_h2(sacc[2*kk][0],   sacc[2*kk][1]);
            const uint32_t a1 = pack_h2(sacc[2*kk][2],   sacc[2*kk][3]);
            const uint32_t a2 = pack_h2(sacc[2*kk+1][0], sacc[2*kk+1][1]);
            const uint32_t a3 = pack_h2(sacc[2*kk+1][2], sacc[2*kk+1][3]);
            #pragma unroll
            for (int p = 0; p < 8; p++) {
                uint32_t b0, b1, b2, b3;
                const uint32_t va = sb + (uint32_t)(vbuf + (p * 16 + r_l) * 144 + (16 * kk + c_l) * 2);
                ldsm_x4(b0, b1, b2, b3, va);
                mma_f16(o[2 * p],     a0, a1, a2, a3, b0, b1);
                mma_f16(o[2 * p + 1], a0, a1, a2, a3, b2, b3);
            }
        }

        __syncthreads();
        if (kt + 2 < 64) {
            load_tile(sb, kbuf, vbuf, cbuf, b, q0, (kt + 2) * 64, tid, conn);
        }
        CP_COMMIT();
    }

    l0 += __shfl_xor_sync(0xffffffffu, l0, 1);
    l0 += __shfl_xor_sync(0xffffffffu, l0, 2);
    l1 += __shfl_xor_sync(0xffffffffu, l1, 1);
    l1 += __shfl_xor_sync(0xffffffffu, l1, 2);
    const float r0 = 1.f / l0, r1 = 1.f / l1;
    float* H0 = g_H + ((size_t)(b * NA + q0 + qw + g)) * ND;
    float* H1 = H0 + 8 * ND;
    #pragma unroll
    for (int nt = 0; nt < 16; nt++) {
        *(float2*)(H0 + nt * 8 + 2 * t) = make_float2(o[nt][0] * r0, o[nt][1] * r0);
        *(float2*)(H1 + nt * 8 + 2 * t) = make_float2(o[nt][2] * r1, o[nt][3] * r1);
    }
}

// ======================= Kernel 3: MLP via mma =======================
// smem: sW1t @0, sW2t @34816, sH @69632, sM @104448, consts @139264
#define MLP_SMEM (4 * 34816 + 4 * 512)

__global__ __launch_bounds__(256, 1)
void mlp_kernel(const float* __restrict__ W1, const float* __restrict__ b1,
                const float* __restrict__ W2, const float* __restrict__ b2,
                const float* __restrict__ gamma, const float* __restrict__ beta,
                float* __restrict__ out) {
    extern __shared__ __align__(16) char smem[];
    const uint32_t sb = smem_u32(smem);
    const int tid = threadIdx.x;
    const int w = tid >> 5, lane = tid & 31;
    const int g = lane >> 2, t = lane & 3;
    const int r_l = ((lane & 16) >> 1) + (lane & 7);
    const int c_l = (lane & 8);
    const int row0 = blockIdx.x * 128;
    const int qw = w * 16;

    float* sb1 = (float*)(smem + 139264);
    float* sb2 = sb1 + 128;
    float* sgm = sb2 + 128;
    float* sbt = sgm + 128;

    load_wt((__half*)(smem + 0),     W1, tid);
    load_wt((__half*)(smem + 34816), W2, tid);
    if (tid < 128) {
        sb1[tid] = b1[tid]; sb2[tid] = b2[tid];
        sgm[tid] = gamma[tid]; sbt[tid] = beta[tid];
    }
    // swish(H) -> fp16 sH
    #pragma unroll 4
    for (int it = 0; it < 16; it++) {
        const int i = tid + it * 256;
        const int r = i >> 5, c4 = (i & 31) * 4;
        const float4 v = *(const float4*)(g_H + (size_t)(row0 + r) * ND + c4);
        uint2 u;
        u.x = pack_h2(swishf(v.x), swishf(v.y));
        u.y = pack_h2(swishf(v.z), swishf(v.w));
        *(uint2*)(smem + 69632 + r * 272 + c4 * 2) = u;
    }
    __syncthreads();

    // A-frags from sH
    uint32_t hf[8][4];
    #pragma unroll
    for (int s = 0; s < 8; s++) {
        const char* base = smem + 69632 + (qw + g) * 272 + (16 * s + 2 * t) * 2;
        hf[s][0] = *(const uint32_t*)(base);
        hf[s][1] = *(const uint32_t*)(base + 8 * 272);
        hf[s][2] = *(const uint32_t*)(base + 16);
        hf[s][3] = *(const uint32_t*)(base + 8 * 272 + 16);
    }

    // GEMM1
    float o1[16][4];
    #pragma unroll
    for (int nt = 0; nt < 16; nt++) { o1[nt][0]=o1[nt][1]=o1[nt][2]=o1[nt][3]=0.f; }
    #pragma unroll
    for (int s = 0; s < 8; s++) {
        #pragma unroll
        for (int p = 0; p < 8; p++) {
            uint32_t b0v, b1v, b2v, b3v;
            ldsm_x4(b0v, b1v, b2v, b3v, sb + (uint32_t)((p * 16 + r_l) * 272 + (16 * s + c_l) * 2));
            mma_f16(o1[2 * p],     hf[s][0], hf[s][1], hf[s][2], hf[s][3], b0v, b1v);
            mma_f16(o1[2 * p + 1], hf[s][0], hf[s][1], hf[s][2], hf[s][3], b2v, b3v);
        }
    }
    // +b1, swish, pack to sM (this warp's rows only)
    #pragma unroll
    for (int nt = 0; nt < 16; nt++) {
        const float2 bb = *(const float2*)(sb1 + nt * 8 + 2 * t);
        const float v0 = swishf(o1[nt][0] + bb.x), v1 = swishf(o1[nt][1] + bb.y);
        const float v2 = swishf(o1[nt][2] + bb.x), v3 = swishf(o1[nt][3] + bb.y);
        *(uint32_t*)(smem + 104448 + (qw + g) * 272 + (nt * 8 + 2 * t) * 2)     = pack_h2(v0, v1);
        *(uint32_t*)(smem + 104448 + (qw + g + 8) * 272 + (nt * 8 + 2 * t) * 2) = pack_h2(v2, v3);
    }
    __syncwarp();

    // A-frags from sM
    uint32_t mf[8][4];
    #pragma unroll
    for (int s = 0; s < 8; s++) {
        const char* base = smem + 104448 + (qw + g) * 272 + (16 * s + 2 * t) * 2;
        mf[s][0] = *(const uint32_t*)(base);
        mf[s][1] = *(const uint32_t*)(base + 8 * 272);
        mf[s][2] = *(const uint32_t*)(base + 16);
        mf[s][3] = *(const uint32_t*)(base + 8 * 272 + 16);
    }

    // GEMM2
    float o2[16][4];
    #pragma unroll
    for (int nt = 0; nt < 16; nt++) { o2[nt][0]=o2[nt][1]=o2[nt][2]=o2[nt][3]=0.f; }
    #pragma unroll
    for (int s = 0; s < 8; s++) {
        #pragma unroll
        for (int p = 0; p < 8; p++) {
            uint32_t b0v, b1v, b2v, b3v;
            ldsm_x4(b0v, b1v, b2v, b3v, sb + 34816u + (uint32_t)((p * 16 + r_l) * 272 + (16 * s + c_l) * 2));
            mma_f16(o2[2 * p],     mf[s][0], mf[s][1], mf[s][2], mf[s][3], b0v, b1v);
            mma_f16(o2[2 * p + 1], mf[s][0], mf[s][1], mf[s][2], mf[s][3], b2v, b3v);
        }
    }
    // +b2, LayerNorm in fragments
    float sum0 = 0.f, sq0 = 0.f, sum1 = 0.f, sq1 = 0.f;
    #pragma unroll
    for (int nt = 0; nt < 16; nt++) {
        const float2 bb = *(const float2*)(sb2 + nt * 8 + 2 * t);
        o2[nt][0] += bb.x; o2[nt][1] += bb.y;
        o2[nt][2] += bb.x; o2[nt][3] += bb.y;
        sum0 += o2[nt][0] + o2[nt][1];
        sq0  += o2[nt][0] * o2[nt][0] + o2[nt][1] * o2[nt][1];
        sum1 += o2[nt][2] + o2[nt][3];
        sq1  += o2[nt][2] * o2[nt][2] + o2[nt][3] * o2[nt][3];
    }
    #pragma unroll
    for (int off = 1; off <= 2; off <<= 1) {
        sum0 += __shfl_xor_sync(0xffffffffu, sum0, off);
        sq0  += __shfl_xor_sync(0xffffffffu, sq0,  off);
        sum1 += __shfl_xor_sync(0xffffffffu, sum1, off);
        sq1  += __shfl_xor_sync(0xffffffffu, sq1,  off);
    }
    const float mu0 = sum0 * 0.0078125f, mu1 = sum1 * 0.0078125f;
    const float rs0 = rsqrtf(sq0 * 0.0078125f - mu0 * mu0 + 1e-5f);
    const float rs1 = rsqrtf(sq1 * 0.0078125f - mu1 * mu1 + 1e-5f);
    float* O0 = out + (size_t)(row0 + qw + g) * ND;
    float* O1 = O0 + 8 * ND;
    #pragma unroll
    for (int nt = 0; nt < 16; nt++) {
        const float2 gm = *(const float2*)(sgm + nt * 8 + 2 * t);
        const float2 bt = *(const float2*)(sbt + nt * 8 + 2 * t);
        *(float2*)(O0 + nt * 8 + 2 * t) = make_float2(
            fmaf((o2[nt][0] - mu0) * rs0, gm.x, bt.x),
            fmaf((o2[nt][1] - mu0) * rs0, gm.y, bt.y));
        *(float2*)(O1 + nt * 8 + 2 * t) = make_float2(
            fmaf((o2[nt][2] - mu1) * rs1, gm.x, bt.x),
            fmaf((o2[nt][3] - mu1) * rs1, gm.y, bt.y));
    }
}

extern "C" void kernel_launch(void* const* d_in, const int* in_sizes, int n_in,
                              void* d_out, int out_size) {
    const float* x     = (const float*)d_in[0];
    const float* conn  = (const float*)d_in[1];
    const float* Wq    = (const float*)d_in[2];
    const float* Wk    = (const float*)d_in[3];
    const float* Wv    = (const float*)d_in[4];
    const float* W1    = (const float*)d_in[5];
    const float* b1    = (const float*)d_in[6];
    const float* W2    = (const float*)d_in[7];
    const float* b2    = (const float*)d_in[8];
    const float* gamma = (const float*)d_in[9];
    const float* beta  = (const float*)d_in[10];
    float* out = (float*)d_out;

    static bool attr_done = false;
    if (!attr_done) {
        cudaFuncSetAttribute(proj_kernel, cudaFuncAttributeMaxDynamicSharedMemorySize, PROJ_SMEM);
        cudaFuncSetAttribute(attn_kernel, cudaFuncAttributeMaxDynamicSharedMemorySize, ATTN_SMEM);
        cudaFuncSetAttribute(mlp_kernel,  cudaFuncAttributeMaxDynamicSharedMemorySize, MLP_SMEM);
        attr_done = true;
    }

    proj_kernel<<<128, 256, PROJ_SMEM>>>(x, Wq, Wk, Wv);
    attn_kernel<<<dim3(32, 4), 256, ATTN_SMEM>>>(conn);
    mlp_kernel<<<128, 256, MLP_SMEM>>>(W1, b1, W2, b2, gamma, beta, out);
}

// round 7
// speedup vs baseline: 3.3748x; 1.1841x over previous
#include <cuda_runtime.h>
#include <cuda_fp16.h>
#include <cstdint>

#define NB 4
#define NA 4096
#define ND 128

__device__ __half g_Qh[NB * NA * ND];
__device__ __half g_Kh[NB * NA * ND];
__device__ __half g_Vt[NB * ND * NA];   // [b][d][a]
__device__ float  g_H [NB * NA * ND];

// ======================= helpers =======================
__device__ __forceinline__ uint32_t smem_u32(const void* p) {
    uint32_t a;
    asm("{ .reg .u64 t; cvta.to.shared.u64 t, %1; cvt.u32.u64 %0, t; }" : "=r"(a) : "l"(p));
    return a;
}
__device__ __forceinline__ void mma_f16(float c[4],
                                        uint32_t a0, uint32_t a1, uint32_t a2, uint32_t a3,
                                        uint32_t b0, uint32_t b1) {
    asm volatile(
        "mma.sync.aligned.m16n8k16.row.col.f32.f16.f16.f32 "
        "{%0,%1,%2,%3},{%4,%5,%6,%7},{%8,%9},{%0,%1,%2,%3};\n"
        : "+f"(c[0]), "+f"(c[1]), "+f"(c[2]), "+f"(c[3])
        : "r"(a0), "r"(a1), "r"(a2), "r"(a3), "r"(b0), "r"(b1));
}
__device__ __forceinline__ void ldsm_x4(uint32_t& r0, uint32_t& r1, uint32_t& r2, uint32_t& r3,
                                        uint32_t addr) {
    asm volatile("ldmatrix.sync.aligned.m8n8.x4.shared.b16 {%0,%1,%2,%3}, [%4];"
                 : "=r"(r0), "=r"(r1), "=r"(r2), "=r"(r3) : "r"(addr));
}
__device__ __forceinline__ void ldsm_x4_t(uint32_t& r0, uint32_t& r1, uint32_t& r2, uint32_t& r3,
                                          uint32_t addr) {
    asm volatile("ldmatrix.sync.aligned.m8n8.x4.trans.shared.b16 {%0,%1,%2,%3}, [%4];"
                 : "=r"(r0), "=r"(r1), "=r"(r2), "=r"(r3) : "r"(addr));
}
__device__ __forceinline__ void cpa16(uint32_t dst, const void* src) {
    asm volatile("cp.async.cg.shared.global [%0], [%1], 16;" :: "r"(dst), "l"(src) : "memory");
}
#define CP_COMMIT() asm volatile("cp.async.commit_group;" ::: "memory")
#define CP_WAIT1()  asm volatile("cp.async.wait_group 1;" ::: "memory")

__device__ __forceinline__ float ex2f(float x) {
    float y; asm("ex2.approx.ftz.f32 %0, %1;" : "=f"(y) : "f"(x)); return y;
}
__device__ __forceinline__ uint32_t pack_h2(float lo, float hi) {
    __half2 h = __floats2half2_rn(lo, hi);
    return *reinterpret_cast<uint32_t*>(&h);
}
__device__ __forceinline__ float swishf(float v) { return v / (1.f + __expf(-v)); }

// convert a 128x128 fp32 weight W (row-major [k][n]) into smem fp16 [k][n], 272B row stride
__device__ __forceinline__ void cvt_w(char* dst, const float* __restrict__ W, int tid) {
    #pragma unroll
    for (int it = 0; it < 16; it++) {
        const int i = tid + it * 256;
        const int r = i >> 5, c4 = (i & 31) * 4;
        const float4 v = *(const float4*)(W + (size_t)i * 4);
        uint2 u;
        u.x = pack_h2(v.x, v.y);
        u.y = pack_h2(v.z, v.w);
        *(uint2*)(dst + r * 272 + c4 * 2) = u;
    }
}

// ======================= Kernel 1: projections via mma (trans-B) =======================
// smem: sX @0, sWq @34816, sWk @69632, sWv @104448, sVst @139264
#define PROJ_SMEM (5 * 34816)

__global__ __launch_bounds__(256, 1)
void proj_kernel(const float* __restrict__ x,
                 const float* __restrict__ Wq,
                 const float* __restrict__ Wk,
                 const float* __restrict__ Wv) {
    extern __shared__ __align__(16) char smem[];
    const uint32_t sb = smem_u32(smem);
    const int tid = threadIdx.x;
    const int w = tid >> 5, lane = tid & 31;
    const int g = lane >> 2, t = lane & 3;
    const int tr_r = lane & 15, tr_c = (lane & 16) >> 1;   // trans-ldsm lane addr
    const int row0 = blockIdx.x * 128;
    const int b = row0 >> 12, a0 = row0 & (NA - 1);
    const int qw = w * 16;

    __half* sVst = (__half*)(smem + 139264);

    // x -> fp16 smem [row][k]
    #pragma unroll 4
    for (int it = 0; it < 16; it++) {
        const int i = tid + it * 256;
        const int r = i >> 5, c4 = (i & 31) * 4;
        const float4 v = *(const float4*)(x + (size_t)(row0 + r) * ND + c4);
        uint2 u;
        u.x = pack_h2(v.x, v.y);
        u.y = pack_h2(v.z, v.w);
        *(uint2*)(smem + r * 272 + c4 * 2) = u;
    }
    cvt_w(smem + 34816,  Wq, tid);
    cvt_w(smem + 69632,  Wk, tid);
    cvt_w(smem + 104448, Wv, tid);
    __syncthreads();

    uint32_t xf[8][4];
    #pragma unroll
    for (int s = 0; s < 8; s++) {
        const char* base = (const char*)smem + (qw + g) * 272 + (16 * s + 2 * t) * 2;
        xf[s][0] = *(const uint32_t*)(base);
        xf[s][1] = *(const uint32_t*)(base + 8 * 272);
        xf[s][2] = *(const uint32_t*)(base + 16);
        xf[s][3] = *(const uint32_t*)(base + 8 * 272 + 16);
    }

    const int gr0 = row0 + qw + g;
    #pragma unroll
    for (int m = 0; m < 3; m++) {
        const uint32_t wb = sb + 34816u * (1 + m);
        float o[16][4];
        #pragma unroll
        for (int nt = 0; nt < 16; nt++) { o[nt][0]=o[nt][1]=o[nt][2]=o[nt][3]=0.f; }
        #pragma unroll
        for (int s = 0; s < 8; s++) {
            #pragma unroll
            for (int p = 0; p < 8; p++) {
                uint32_t b0, b1, b2, b3;
                ldsm_x4_t(b0, b1, b2, b3, wb + (uint32_t)((16 * s + tr_r) * 272 + (p * 16 + tr_c) * 2));
                mma_f16(o[2 * p],     xf[s][0], xf[s][1], xf[s][2], xf[s][3], b0, b1);
                mma_f16(o[2 * p + 1], xf[s][0], xf[s][1], xf[s][2], xf[s][3], b2, b3);
            }
        }
        if (m < 2) {
            __half* dst = (m == 0) ? g_Qh : g_Kh;
            #pragma unroll
            for (int nt = 0; nt < 16; nt++) {
                *(uint32_t*)(dst + (size_t)gr0 * ND + nt * 8 + 2 * t)       = pack_h2(o[nt][0], o[nt][1]);
                *(uint32_t*)(dst + (size_t)(gr0 + 8) * ND + nt * 8 + 2 * t) = pack_h2(o[nt][2], o[nt][3]);
            }
        } else {
            #pragma unroll
            for (int nt = 0; nt < 16; nt++) {
                *(uint32_t*)((char*)sVst + (qw + g) * 272 + (nt * 8 + 2 * t) * 2)     = pack_h2(o[nt][0], o[nt][1]);
                *(uint32_t*)((char*)sVst + (qw + g + 8) * 272 + (nt * 8 + 2 * t) * 2) = pack_h2(o[nt][2], o[nt][3]);
            }
        }
    }
    __syncthreads();
    const int c = tid & 127, dgrp = tid >> 7;
    #pragma unroll 4
    for (int k = 0; k < 64; k++) {
        const int dd = dgrp * 64 + k;
        g_Vt[((size_t)(b * ND + dd)) * NA + a0 + c] = sVst[c * 136 + dd];
    }
}

// ======================= Kernel 2: flash attention (chunk-pipelined) =======================
#define SM_Q  0
#define SM_K0 34816
#define SM_K1 (SM_K0 + 17408)
#define SM_V0 (SM_K1 + 17408)
#define SM_V1 (SM_V0 + 18432)
#define SM_C0 (SM_V1 + 18432)
#define SM_C1 (SM_C0 + 34816)
#define ATTN_SMEM (SM_C1 + 34816)

__device__ __forceinline__ void load_tile(uint32_t sb, int kbuf, int vbuf, int cbuf,
                                          int b, int q0, int k0, int tid,
                                          const float* __restrict__ conn) {
    const __half* Kg = g_Kh + ((size_t)(b * NA + k0)) * ND;
    #pragma unroll
    for (int i = tid; i < 1024; i += 256) {
        const int r = i >> 4, c = i & 15;
        cpa16(sb + (uint32_t)(kbuf + r * 272 + c * 16), Kg + r * ND + c * 8);
    }
    const __half* Vg = g_Vt + ((size_t)(b * ND)) * NA + k0;
    #pragma unroll
    for (int i = tid; i < 1024; i += 256) {
        const int r = i >> 3, c = i & 7;
        cpa16(sb + (uint32_t)(vbuf + r * 144 + c * 16), Vg + (size_t)r * NA + c * 8);
    }
    const float* Cg = conn + ((size_t)(b * NA + q0)) * NA + k0;
    #pragma unroll
    for (int i = tid; i < 2048; i += 256) {
        const int r = i >> 4, c = i & 15;
        cpa16(sb + (uint32_t)(cbuf + r * 272 + c * 16), Cg + (size_t)r * NA + c * 4);
    }
}

__global__ __launch_bounds__(256, 1)
void attn_kernel(const float* __restrict__ conn) {
    extern __shared__ __align__(16) char smem[];
    const uint32_t sb = smem_u32(smem);
    const int tid = threadIdx.x;
    const int w = tid >> 5, lane = tid & 31;
    const int g = lane >> 2, t = lane & 3;
    const int b = blockIdx.y;
    const int q0 = blockIdx.x * 128;
    const int qw = w * 16;
    const int r_l = ((lane & 16) >> 1) + (lane & 7);
    const int c_l = (lane & 8);

    {
        const __half* Qg = g_Qh + ((size_t)(b * NA + q0)) * ND;
        #pragma unroll
        for (int i = tid; i < 2048; i += 256) {
            const int r = i >> 4, c = i & 15;
            cpa16(sb + (uint32_t)(SM_Q + r * 272 + c * 16), Qg + r * ND + c * 8);
        }
    }
    load_tile(sb, SM_K0, SM_V0, SM_C0, b, q0, 0, tid, conn);
    CP_COMMIT();
    load_tile(sb, SM_K1, SM_V1, SM_C1, b, q0, 64, tid, conn);
    CP_COMMIT();

    CP_WAIT1();
    __syncthreads();

    uint32_t qf[8][4];
    #pragma unroll
    for (int s = 0; s < 8; s++) {
        const char* base = smem + SM_Q + (qw + g) * 272 + (16 * s + 2 * t) * 2;
        qf[s][0] = *(const uint32_t*)(base);
        qf[s][1] = *(const uint32_t*)(base + 8 * 272);
        qf[s][2] = *(const uint32_t*)(base + 16);
        qf[s][3] = *(const uint32_t*)(base + 8 * 272 + 16);
    }

    float o[16][4];
    #pragma unroll
    for (int nt = 0; nt < 16; nt++) { o[nt][0]=o[nt][1]=o[nt][2]=o[nt][3]=0.f; }
    float l0 = 0.f, l1 = 0.f;

    const float K1c = 0.08838834764831845f * 1.44269504088896340f;
    const float K2c = 1.44269504088896340f;

    for (int kt = 0; kt < 64; kt++) {
        const int kbuf = (kt & 1) ? SM_K1 : SM_K0;
        const int vbuf = (kt & 1) ? SM_V1 : SM_V0;
        const int cbuf = (kt & 1) ? SM_C1 : SM_C0;
        CP_WAIT1();
        __syncthreads();

        float sacc[8][4];
        #pragma unroll
        for (int nt = 0; nt < 8; nt++) { sacc[nt][0]=sacc[nt][1]=sacc[nt][2]=sacc[nt][3]=0.f; }

        // ---- S chunk A: keys 0-31 (p = 0,1) ----
        #pragma unroll
        for (int s = 0; s < 8; s++) {
            #pragma unroll
            for (int p = 0; p < 2; p++) {
                uint32_t b0, b1, b2, b3;
                ldsm_x4(b0, b1, b2, b3,
                        sb + (uint32_t)(kbuf + (p * 16 + r_l) * 272 + (16 * s + c_l) * 2));
                mma_f16(sacc[2 * p],     qf[s][0], qf[s][1], qf[s][2], qf[s][3], b0, b1);
                mma_f16(sacc[2 * p + 1], qf[s][0], qf[s][1], qf[s][2], qf[s][3], b2, b3);
            }
        }
        // ---- S chunk B: keys 32-63 (p = 2,3) ----
        #pragma unroll
        for (int s = 0; s < 8; s++) {
            #pragma unroll
            for (int p = 2; p < 4; p++) {
                uint32_t b0, b1, b2, b3;
                ldsm_x4(b0, b1, b2, b3,
                        sb + (uint32_t)(kbuf + (p * 16 + r_l) * 272 + (16 * s + c_l) * 2));
                mma_f16(sacc[2 * p],     qf[s][0], qf[s][1], qf[s][2], qf[s][3], b0, b1);
                mma_f16(sacc[2 * p + 1], qf[s][0], qf[s][1], qf[s][2], qf[s][3], b2, b3);
            }
        }

        const float* c0p = (const float*)(smem + cbuf) + (qw + g) * 68 + 2 * t;
        const float* c1p = c0p + 8 * 68;

        // ---- epilogue A (overlaps S chunk B in flight) ----
        #pragma unroll
        for (int nt = 0; nt < 4; nt++) {
            const float2 v0 = *(const float2*)(c0p + nt * 8);
            const float2 v1 = *(const float2*)(c1p + nt * 8);
            sacc[nt][0] = ex2f(fmaf(sacc[nt][0], K1c, v0.x * K2c));
            sacc[nt][1] = ex2f(fmaf(sacc[nt][1], K1c, v0.y * K2c));
            sacc[nt][2] = ex2f(fmaf(sacc[nt][2], K1c, v1.x * K2c));
            sacc[nt][3] = ex2f(fmaf(sacc[nt][3], K1c, v1.y * K2c));
            l0 += sacc[nt][0] + sacc[nt][1];
            l1 += sacc[nt][2] + sacc[nt][3];
        }
        // ---- PV chunk A (kk = 0,1) ----
        #pragma unroll
        for (int kk = 0; kk < 2; kk++) {
            const uint32_t a0 = pack_h2(sacc[2*kk][0],   sacc[2*kk][1]);
            const uint32_t a1 = pack_h2(sacc[2*kk][2],   sacc[2*kk][3]);
            const uint32_t a2 = pack_h2(sacc[2*kk+1][0], sacc[2*kk+1][1]);
            const uint32_t a3 = pack_h2(sacc[2*kk+1][2], sacc[2*kk+1][3]);
            #pragma unroll
            for (int p = 0; p < 8; p++) {
                uint32_t b0, b1, b2, b3;
                ldsm_x4(b0, b1, b2, b3,
                        sb + (uint32_t)(vbuf + (p * 16 + r_l) * 144 + (16 * kk + c_l) * 2));
                mma_f16(o[2 * p],     a0, a1, a2, a3, b0, b1);
                mma_f16(o[2 * p + 1], a0, a1, a2, a3, b2, b3);
            }
        }
        // ---- epilogue B (overlaps PV chunk A in flight) ----
        #pragma unroll
        for (int nt = 4; nt < 8; nt++) {
            const float2 v0 = *(const float2*)(c0p + nt * 8);
            const float2 v1 = *(const float2*)(c1p + nt * 8);
            sacc[nt][0] = ex2f(fmaf(sacc[nt][0], K1c, v0.x * K2c));
            sacc[nt][1] = ex2f(fmaf(sacc[nt][1], K1c, v0.y * K2c));
            sacc[nt][2] = ex2f(fmaf(sacc[nt][2], K1c, v1.x * K2c));
            sacc[nt][3] = ex2f(fmaf(sacc[nt][3], K1c, v1.y * K2c));
            l0 += sacc[nt][0] + sacc[nt][1];
            l1 += sacc[nt][2] + sacc[nt][3];
        }
        // ---- PV chunk B (kk = 2,3) ----
        #pragma unroll
        for (int kk = 2; kk < 4; kk++) {
            const uint32_t a0 = pack_h2(sacc[2*kk][0],   sacc[2*kk][1]);
            const uint32_t a1 = pack_h2(sacc[2*kk][2],   sacc[2*kk][3]);
            const uint32_t a2 = pack_h2(sacc[2*kk+1][0], sacc[2*kk+1][1]);
            const uint32_t a3 = pack_h2(sacc[2*kk+1][2], sacc[2*kk+1][3]);
            #pragma unroll
            for (int p = 0; p < 8; p++) {
                uint32_t b0, b1, b2, b3;
                ldsm_x4(b0, b1, b2, b3,
                        sb + (uint32_t)(vbuf + (p * 16 + r_l) * 144 + (16 * kk + c_l) * 2));
                mma_f16(o[2 * p],     a0, a1, a2, a3, b0, b1);
                mma_f16(o[2 * p + 1], a0, a1, a2, a3, b2, b3);
            }
        }

        __syncthreads();
        if (kt + 2 < 64) {
            load_tile(sb, kbuf, vbuf, cbuf, b, q0, (kt + 2) * 64, tid, conn);
        }
        CP_COMMIT();
    }

    l0 += __shfl_xor_sync(0xffffffffu, l0, 1);
    l0 += __shfl_xor_sync(0xffffffffu, l0, 2);
    l1 += __shfl_xor_sync(0xffffffffu, l1, 1);
    l1 += __shfl_xor_sync(0xffffffffu, l1, 2);
    const float r0 = 1.f / l0, r1 = 1.f / l1;
    float* H0 = g_H + ((size_t)(b * NA + q0 + qw + g)) * ND;
    float* H1 = H0 + 8 * ND;
    #pragma unroll
    for (int nt = 0; nt < 16; nt++) {
        *(float2*)(H0 + nt * 8 + 2 * t) = make_float2(o[nt][0] * r0, o[nt][1] * r0);
        *(float2*)(H1 + nt * 8 + 2 * t) = make_float2(o[nt][2] * r1, o[nt][3] * r1);
    }
}

// ======================= Kernel 3: MLP via mma (trans-B) =======================
#define MLP_SMEM (4 * 34816 + 4 * 512)

__global__ __launch_bounds__(256, 1)
void mlp_kernel(const float* __restrict__ W1, const float* __restrict__ b1,
                const float* __restrict__ W2, const float* __restrict__ b2,
                const float* __restrict__ gamma, const float* __restrict__ beta,
                float* __restrict__ out) {
    extern __shared__ __align__(16) char smem[];
    const uint32_t sb = smem_u32(smem);
    const int tid = threadIdx.x;
    const int w = tid >> 5, lane = tid & 31;
    const int g = lane >> 2, t = lane & 3;
    const int tr_r = lane & 15, tr_c = (lane & 16) >> 1;
    const int row0 = blockIdx.x * 128;
    const int qw = w * 16;

    float* sb1 = (float*)(smem + 139264);
    float* sb2 = sb1 + 128;
    float* sgm = sb2 + 128;
    float* sbt = sgm + 128;

    cvt_w(smem + 0,     W1, tid);
    cvt_w(smem + 34816, W2, tid);
    if (tid < 128) {
        sb1[tid] = b1[tid]; sb2[tid] = b2[tid];
        sgm[tid] = gamma[tid]; sbt[tid] = beta[tid];
    }
    #pragma unroll 4
    for (int it = 0; it < 16; it++) {
        const int i = tid + it * 256;
        const int r = i >> 5, c4 = (i & 31) * 4;
        const float4 v = *(const float4*)(g_H + (size_t)(row0 + r) * ND + c4);
        uint2 u;
        u.x = pack_h2(swishf(v.x), swishf(v.y));
        u.y = pack_h2(swishf(v.z), swishf(v.w));
        *(uint2*)(smem + 69632 + r * 272 + c4 * 2) = u;
    }
    __syncthreads();

    uint32_t hf[8][4];
    #pragma unroll
    for (int s = 0; s < 8; s++) {
        const char* base = smem + 69632 + (qw + g) * 272 + (16 * s + 2 * t) * 2;
        hf[s][0] = *(const uint32_t*)(base);
        hf[s][1] = *(const uint32_t*)(base + 8 * 272);
        hf[s][2] = *(const uint32_t*)(base + 16);
        hf[s][3] = *(const uint32_t*)(base + 8 * 272 + 16);
    }

    float o1[16][4];
    #pragma unroll
    for (int nt = 0; nt < 16; nt++) { o1[nt][0]=o1[nt][1]=o1[nt][2]=o1[nt][3]=0.f; }
    #pragma unroll
    for (int s = 0; s < 8; s++) {
        #pragma unroll
        for (int p = 0; p < 8; p++) {
            uint32_t b0v, b1v, b2v, b3v;
            ldsm_x4_t(b0v, b1v, b2v, b3v, sb + (uint32_t)((16 * s + tr_r) * 272 + (p * 16 + tr_c) * 2));
            mma_f16(o1[2 * p],     hf[s][0], hf[s][1], hf[s][2], hf[s][3], b0v, b1v);
            mma_f16(o1[2 * p + 1], hf[s][0], hf[s][1], hf[s][2], hf[s][3], b2v, b3v);
        }
    }
    #pragma unroll
    for (int nt = 0; nt < 16; nt++) {
        const float2 bb = *(const float2*)(sb1 + nt * 8 + 2 * t);
        const float v0 = swishf(o1[nt][0] + bb.x), v1 = swishf(o1[nt][1] + bb.y);
        const float v2 = swishf(o1[nt][2] + bb.x), v3 = swishf(o1[nt][3] + bb.y);
        *(uint32_t*)(smem + 104448 + (qw + g) * 272 + (nt * 8 + 2 * t) * 2)     = pack_h2(v0, v1);
        *(uint32_t*)(smem + 104448 + (qw + g + 8) * 272 + (nt * 8 + 2 * t) * 2) = pack_h2(v2, v3);
    }
    __syncwarp();

    uint32_t mf[8][4];
    #pragma unroll
    for (int s = 0; s < 8; s++) {
        const char* base = smem + 104448 + (qw + g) * 272 + (16 * s + 2 * t) * 2;
        mf[s][0] = *(const uint32_t*)(base);
        mf[s][1] = *(const uint32_t*)(base + 8 * 272);
        mf[s][2] = *(const uint32_t*)(base + 16);
        mf[s][3] = *(const uint32_t*)(base + 8 * 272 + 16);
    }

    float o2[16][4];
    #pragma unroll
    for (int nt = 0; nt < 16; nt++) { o2[nt][0]=o2[nt][1]=o2[nt][2]=o2[nt][3]=0.f; }
    #pragma unroll
    for (int s = 0; s < 8; s++) {
        #pragma unroll
        for (int p = 0; p < 8; p++) {
            uint32_t b0v, b1v, b2v, b3v;
            ldsm_x4_t(b0v, b1v, b2v, b3v, sb + 34816u + (uint32_t)((16 * s + tr_r) * 272 + (p * 16 + tr_c) * 2));
            mma_f16(o2[2 * p],     mf[s][0], mf[s][1], mf[s][2], mf[s][3], b0v, b1v);
            mma_f16(o2[2 * p + 1], mf[s][0], mf[s][1], mf[s][2], mf[s][3], b2v, b3v);
        }
    }
    float sum0 = 0.f, sq0 = 0.f, sum1 = 0.f, sq1 = 0.f;
    #pragma unroll
    for (int nt = 0; nt < 16; nt++) {
        const float2 bb = *(const float2*)(sb2 + nt * 8 + 2 * t);
        o2[nt][0] += bb.x; o2[nt][1] += bb.y;
        o2[nt][2] += bb.x; o2[nt][3] += bb.y;
        sum0 += o2[nt][0] + o2[nt][1];
        sq0  += o2[nt][0] * o2[nt][0] + o2[nt][1] * o2[nt][1];
        sum1 += o2[nt][2] + o2[nt][3];
        sq1  += o2[nt][2] * o2[nt][2] + o2[nt][3] * o2[nt][3];
    }
    #pragma unroll
    for (int off = 1; off <= 2; off <<= 1) {
        sum0 += __shfl_xor_sync(0xffffffffu, sum0, off);
        sq0  += __shfl_xor_sync(0xffffffffu, sq0,  off);
        sum1 += __shfl_xor_sync(0xffffffffu, sum1, off);
        sq1  += __shfl_xor_sync(0xffffffffu, sq1,  off);
    }
    const float mu0 = sum0 * 0.0078125f, mu1 = sum1 * 0.0078125f;
    const float rs0 = rsqrtf(sq0 * 0.0078125f - mu0 * mu0 + 1e-5f);
    const float rs1 = rsqrtf(sq1 * 0.0078125f - mu1 * mu1 + 1e-5f);
    float* O0 = out + (size_t)(row0 + qw + g) * ND;
    float* O1 = O0 + 8 * ND;
    #pragma unroll
    for (int nt = 0; nt < 16; nt++) {
        const float2 gm = *(const float2*)(sgm + nt * 8 + 2 * t);
        const float2 bt = *(const float2*)(sbt + nt * 8 + 2 * t);
        *(float2*)(O0 + nt * 8 + 2 * t) = make_float2(
            fmaf((o2[nt][0] - mu0) * rs0, gm.x, bt.x),
            fmaf((o2[nt][1] - mu0) * rs0, gm.y, bt.y));
        *(float2*)(O1 + nt * 8 + 2 * t) = make_float2(
            fmaf((o2[nt][2] - mu1) * rs1, gm.x, bt.x),
            fmaf((o2[nt][3] - mu1) * rs1, gm.y, bt.y));
    }
}

extern "C" void kernel_launch(void* const* d_in, const int* in_sizes, int n_in,
                              void* d_out, int out_size) {
    const float* x     = (const float*)d_in[0];
    const float* conn  = (const float*)d_in[1];
    const float* Wq    = (const float*)d_in[2];
    const float* Wk    = (const float*)d_in[3];
    const float* Wv    = (const float*)d_in[4];
    const float* W1    = (const float*)d_in[5];
    const float* b1    = (const float*)d_in[6];
    const float* W2    = (const float*)d_in[7];
    const float* b2    = (const float*)d_in[8];
    const float* gamma = (const float*)d_in[9];
    const float* beta  = (const float*)d_in[10];
    float* out = (float*)d_out;

    static bool attr_done = false;
    if (!attr_done) {
        cudaFuncSetAttribute(proj_kernel, cudaFuncAttributeMaxDynamicSharedMemorySize, PROJ_SMEM);
        cudaFuncSetAttribute(attn_kernel, cudaFuncAttributeMaxDynamicSharedMemorySize, ATTN_SMEM);
        cudaFuncSetAttribute(mlp_kernel,  cudaFuncAttributeMaxDynamicSharedMemorySize, MLP_SMEM);
        attr_done = true;
    }

    proj_kernel<<<128, 256, PROJ_SMEM>>>(x, Wq, Wk, Wv);
    attn_kernel<<<dim3(32, 4), 256, ATTN_SMEM>>>(conn);
    mlp_kernel<<<128, 256, MLP_SMEM>>>(W1, b1, W2, b2, gamma, beta, out);
}